// round 10
// baseline (speedup 1.0000x reference)
#include <cuda_runtime.h>
#include <cuda_bf16.h>
#include <cstdint>

#define N_NODES 20000
#define N_EDGES 640000
#define C 128
#define NUM_GRAPHS 64
#define CAP 128                        // bucket capacity per node (max deg ~58)

// ---------------- scratch (no allocations allowed) ----------------
__device__ __nv_bfloat16 g_xb[N_NODES * C];  // bf16 copy of x (gather source, layer 1)
__device__ __nv_bfloat16 g_hb[N_NODES * C];  // bf16 h1 (gather source, layer 2)
__device__ float g_Wt[4][C * C];       // tf32-pre-rounded W1a, W1b, W2a, W2b
__device__ float g_gsum[NUM_GRAPHS * C];
__device__ float g_gcnt[NUM_GRAPHS];
__device__ int   g_csrc[N_NODES * CAP];// bucketed adjacency: src ids of node n at [n*CAP ...]
__device__ int   g_deg[N_NODES];
__device__ int   g_batch[N_NODES];
__device__ int   g_is64;

// ---------------- tf32 / bf16 helpers ----------------
__device__ __forceinline__ float tf32r(float x) {
    uint32_t u; asm("cvt.rna.tf32.f32 %0, %1;" : "=r"(u) : "f"(x));
    return __uint_as_float(u);
}
__device__ __forceinline__ void mma8(float* c, uint32_t a0, uint32_t a1, uint32_t a2,
                                     uint32_t a3, uint32_t b0, uint32_t b1) {
    asm volatile("mma.sync.aligned.m16n8k8.row.col.f32.tf32.tf32.f32 "
                 "{%0,%1,%2,%3}, {%4,%5,%6,%7}, {%8,%9}, {%0,%1,%2,%3};"
                 : "+f"(c[0]), "+f"(c[1]), "+f"(c[2]), "+f"(c[3])
                 : "r"(a0), "r"(a1), "r"(a2), "r"(a3), "r"(b0), "r"(b1));
}
// load 4 bf16 channels (8 bytes) -> float4
__device__ __forceinline__ float4 ld_bf4(const __nv_bfloat16* p) {
    uint2 u = *(const uint2*)p;
    __nv_bfloat162 lo = *reinterpret_cast<__nv_bfloat162*>(&u.x);
    __nv_bfloat162 hi = *reinterpret_cast<__nv_bfloat162*>(&u.y);
    float2 f0 = __bfloat1622float2(lo);
    float2 f1 = __bfloat1622float2(hi);
    return make_float4(f0.x, f0.y, f1.x, f1.y);
}

// ---------------- setup: zero accumulators + detect index dtype ----------------
__global__ void setup_kernel(const int* __restrict__ eidx_raw) {
    int i = blockIdx.x * blockDim.x + threadIdx.x;
    if (i < N_NODES) g_deg[i] = 0;
    if (i < NUM_GRAPHS * C) g_gsum[i] = 0.f;
    if (i < NUM_GRAPHS) g_gcnt[i] = 0.f;
    if (i == 0) {
        int any = 0;
#pragma unroll
        for (int k = 1; k < 128; k += 2) any |= eidx_raw[k];
        g_is64 = (any == 0) ? 1 : 0;
    }
}

// ---------------- pre-round all W to tf32 (once) ----------------
__global__ void preround_w(const float* __restrict__ W1a, const float* __restrict__ W1b,
                           const float* __restrict__ W2a, const float* __restrict__ W2b) {
    int i = blockIdx.x * blockDim.x + threadIdx.x;      // float4 index, 0..16383
    int which = i >> 12;                                // 4096 float4 per W
    int idx = i & 4095;
    const float* src = (which == 0) ? W1a : (which == 1) ? W1b : (which == 2) ? W2a : W2b;
    float4 v = ((const float4*)src)[idx];
    ((float4*)g_Wt[which])[idx] =
        make_float4(tf32r(v.x), tf32r(v.y), tf32r(v.z), tf32r(v.w));
}

// ---------------- convert x -> bf16 (once) ----------------
__global__ void convert_x(const float* __restrict__ x) {
    int i = blockIdx.x * blockDim.x + threadIdx.x;      // 8 floats per thread
    if (i < N_NODES * C / 8) {
        float4 a = ((const float4*)x)[i * 2];
        float4 b = ((const float4*)x)[i * 2 + 1];
        uint4 o;
        __nv_bfloat162 p0 = __float22bfloat162_rn(make_float2(a.x, a.y));
        __nv_bfloat162 p1 = __float22bfloat162_rn(make_float2(a.z, a.w));
        __nv_bfloat162 p2 = __float22bfloat162_rn(make_float2(b.x, b.y));
        __nv_bfloat162 p3 = __float22bfloat162_rn(make_float2(b.z, b.w));
        o.x = *reinterpret_cast<uint32_t*>(&p0);
        o.y = *reinterpret_cast<uint32_t*>(&p1);
        o.z = *reinterpret_cast<uint32_t*>(&p2);
        o.w = *reinterpret_cast<uint32_t*>(&p3);
        ((uint4*)g_xb)[i] = o;
    }
}

// ---------------- build adjacency: convert + histogram + bucket-scatter, one pass ----------------
__global__ void build_adj(const void* __restrict__ eidx,
                          const void* __restrict__ batch) {
    int i0 = (blockIdx.x * blockDim.x + threadIdx.x) * 4;
    int4 s, d;
    bool have_edges = (i0 < N_EDGES);
    if (g_is64) {
        const long long* e = (const long long*)eidx;
        if (have_edges) {
            longlong2 s01 = *(const longlong2*)&e[i0];
            longlong2 s23 = *(const longlong2*)&e[i0 + 2];
            longlong2 d01 = *(const longlong2*)&e[N_EDGES + i0];
            longlong2 d23 = *(const longlong2*)&e[N_EDGES + i0 + 2];
            s = make_int4((int)s01.x, (int)s01.y, (int)s23.x, (int)s23.y);
            d = make_int4((int)d01.x, (int)d01.y, (int)d23.x, (int)d23.y);
        }
        if (i0 < N_NODES) {
            const long long* b = (const long long*)batch;
            longlong2 b01 = *(const longlong2*)&b[i0];
            longlong2 b23 = *(const longlong2*)&b[i0 + 2];
            int4 g = make_int4((int)b01.x, (int)b01.y, (int)b23.x, (int)b23.y);
            *(int4*)&g_batch[i0] = g;
            atomicAdd(&g_gcnt[g.x], 1.f); atomicAdd(&g_gcnt[g.y], 1.f);
            atomicAdd(&g_gcnt[g.z], 1.f); atomicAdd(&g_gcnt[g.w], 1.f);
        }
    } else {
        const int* e = (const int*)eidx;
        if (have_edges) {
            s = *(const int4*)&e[i0];
            d = *(const int4*)&e[N_EDGES + i0];
        }
        if (i0 < N_NODES) {
            int4 g = *(const int4*)&((const int*)batch)[i0];
            *(int4*)&g_batch[i0] = g;
            atomicAdd(&g_gcnt[g.x], 1.f); atomicAdd(&g_gcnt[g.y], 1.f);
            atomicAdd(&g_gcnt[g.z], 1.f); atomicAdd(&g_gcnt[g.w], 1.f);
        }
    }
    if (have_edges) {
        int r0 = atomicAdd(&g_deg[d.x], 1);
        int r1 = atomicAdd(&g_deg[d.y], 1);
        int r2 = atomicAdd(&g_deg[d.z], 1);
        int r3 = atomicAdd(&g_deg[d.w], 1);
        if (r0 < CAP) g_csrc[d.x * CAP + r0] = s.x;
        if (r1 < CAP) g_csrc[d.y * CAP + r1] = s.y;
        if (r2 < CAP) g_csrc[d.z * CAP + r2] = s.z;
        if (r3 < CAP) g_csrc[d.w * CAP + r3] = s.w;
    }
}

// ---------------- fused conv layer (tensor-core GEMMs, 32-row tiles) ----------------
#define TILE_ROWS 32
#define ASTR 132     // A/T tile stride: A-frag LDS bank = lane (conflict-free)
#define WSTR 136     // W tile stride: B-frag LDS bank = 8k+q (conflict-free)
#define CONV_SMEM ((128 * WSTR + TILE_ROWS * ASTR) * 4)

// warp tile: m16 x n32, k=128 in 8-steps; operands already tf32-rounded in smem.
__device__ __forceinline__ void gemm_tile(const float* __restrict__ As,
                                          const float* __restrict__ Ws,
                                          float acc[4][4],
                                          int m_base, int n_base, int qid, int tid4)
{
#pragma unroll
    for (int nt = 0; nt < 4; ++nt)
#pragma unroll
        for (int j = 0; j < 4; ++j) acc[nt][j] = 0.f;

#pragma unroll
    for (int k0 = 0; k0 < 128; k0 += 8) {
        const float* ar0 = &As[(m_base + qid) * ASTR + k0 + tid4];
        const float* ar1 = &As[(m_base + qid + 8) * ASTR + k0 + tid4];
        uint32_t a0 = __float_as_uint(ar0[0]);
        uint32_t a1 = __float_as_uint(ar1[0]);
        uint32_t a2 = __float_as_uint(ar0[4]);
        uint32_t a3 = __float_as_uint(ar1[4]);
        const float* wr0 = &Ws[(k0 + tid4) * WSTR + n_base + qid];
        const float* wr1 = wr0 + 4 * WSTR;
#pragma unroll
        for (int nt = 0; nt < 4; ++nt) {
            uint32_t b0 = __float_as_uint(wr0[nt * 8]);
            uint32_t b1 = __float_as_uint(wr1[nt * 8]);
            mma8(acc[nt], a0, a1, a2, a3, b0, b1);
        }
    }
}

__global__ void __launch_bounds__(256, 2) fused_conv(
    const __nv_bfloat16* __restrict__ feat,     // bf16 feature table (gather source)
    const float* __restrict__ Wa, const float* __restrict__ ba,
    const float* __restrict__ Wb, const float* __restrict__ bb,
    __nv_bfloat16* __restrict__ outb, int do_pool)
{
    extern __shared__ float sm[];
    float* Ws = sm;                       // [128][WSTR]
    float* As = sm + 128 * WSTR;          // [32][ASTR] (A tile, then T tile)

    const int t = threadIdx.x;
    const int m0 = blockIdx.x * TILE_ROWS;
    const int lane = t & 31;
    const int w = t >> 5;

    // ---- load Wa (already tf32-rounded): pure float4 copy
#pragma unroll
    for (int i = 0; i < 16; ++i) {
        int idx = t + i * 256;
        float4 v = ((const float4*)Wa)[idx];
        int kk = idx >> 5;
        int nn = (idx & 31) * 4;
        *(float4*)&Ws[kk * WSTR + nn] = v;
    }

    // ---- gather: warp per node, 4 nodes per warp; folds "+x" (GIN eps=0)
    // bf16 loads (8B/lane), fp32 accumulation, tf32-rounded at smem write.
#pragma unroll
    for (int i = 0; i < 4; ++i) {
        int r = w * 4 + i;                // local row 0..31
        int node = m0 + r;                // always < N_NODES (20000 = 625*32)
        float4 acc4 = ld_bf4(&feat[(size_t)node * C + lane * 4]);
        const int* adj = &g_csrc[node * CAP];
        int deg = g_deg[node];
        if (deg > CAP) deg = CAP;
        int e = 0;
        for (; e + 8 <= deg; e += 8) {
            int s0 = adj[e + 0];
            int s1 = adj[e + 1];
            int s2 = adj[e + 2];
            int s3 = adj[e + 3];
            int s4 = adj[e + 4];
            int s5 = adj[e + 5];
            int s6 = adj[e + 6];
            int s7 = adj[e + 7];
            float4 v0 = ld_bf4(&feat[(size_t)s0 * C + lane * 4]);
            float4 v1 = ld_bf4(&feat[(size_t)s1 * C + lane * 4]);
            float4 v2 = ld_bf4(&feat[(size_t)s2 * C + lane * 4]);
            float4 v3 = ld_bf4(&feat[(size_t)s3 * C + lane * 4]);
            float4 v4 = ld_bf4(&feat[(size_t)s4 * C + lane * 4]);
            float4 v5 = ld_bf4(&feat[(size_t)s5 * C + lane * 4]);
            float4 v6 = ld_bf4(&feat[(size_t)s6 * C + lane * 4]);
            float4 v7 = ld_bf4(&feat[(size_t)s7 * C + lane * 4]);
            acc4.x += (v0.x + v1.x + v2.x + v3.x) + (v4.x + v5.x + v6.x + v7.x);
            acc4.y += (v0.y + v1.y + v2.y + v3.y) + (v4.y + v5.y + v6.y + v7.y);
            acc4.z += (v0.z + v1.z + v2.z + v3.z) + (v4.z + v5.z + v6.z + v7.z);
            acc4.w += (v0.w + v1.w + v2.w + v3.w) + (v4.w + v5.w + v6.w + v7.w);
        }
        for (; e + 2 <= deg; e += 2) {
            int s0 = adj[e + 0];
            int s1 = adj[e + 1];
            float4 v0 = ld_bf4(&feat[(size_t)s0 * C + lane * 4]);
            float4 v1 = ld_bf4(&feat[(size_t)s1 * C + lane * 4]);
            acc4.x += v0.x + v1.x;
            acc4.y += v0.y + v1.y;
            acc4.z += v0.z + v1.z;
            acc4.w += v0.w + v1.w;
        }
        if (e < deg) {
            float4 v = ld_bf4(&feat[(size_t)adj[e] * C + lane * 4]);
            acc4.x += v.x; acc4.y += v.y; acc4.z += v.z; acc4.w += v.w;
        }
        *((float4*)&As[r * ASTR + lane * 4]) =
            make_float4(tf32r(acc4.x), tf32r(acc4.y), tf32r(acc4.z), tf32r(acc4.w));
    }
    __syncthreads();

    const int warp_m = w & 1;             // 2 warps along M (16 rows each)
    const int warp_n = w >> 1;            // 4 warps along N (32 cols each)
    const int m_base = warp_m * 16;
    const int n_base = warp_n * 32;
    const int qid = lane >> 2;
    const int tid4 = lane & 3;

    float acc[4][4];

    // ---- GEMM1
    gemm_tile(As, Ws, acc, m_base, n_base, qid, tid4);
    __syncthreads();   // all GEMM1 reads of As & Ws complete

    // ---- t = tf32(relu(acc + ba)) -> As ; reload Ws with Wb (pure copy)
#pragma unroll
    for (int nt = 0; nt < 4; ++nt) {
        int col = n_base + nt * 8 + 2 * tid4;
        float2 bv = *(const float2*)&ba[col];
        int r0 = m_base + qid, r1 = r0 + 8;
        *(float2*)&As[r0 * ASTR + col] =
            make_float2(tf32r(fmaxf(acc[nt][0] + bv.x, 0.f)),
                        tf32r(fmaxf(acc[nt][1] + bv.y, 0.f)));
        *(float2*)&As[r1 * ASTR + col] =
            make_float2(tf32r(fmaxf(acc[nt][2] + bv.x, 0.f)),
                        tf32r(fmaxf(acc[nt][3] + bv.y, 0.f)));
    }
#pragma unroll
    for (int i = 0; i < 16; ++i) {
        int idx = t + i * 256;
        float4 v = ((const float4*)Wb)[idx];
        int kk = idx >> 5;
        int nn = (idx & 31) * 4;
        *(float4*)&Ws[kk * WSTR + nn] = v;
    }
    __syncthreads();

    // ---- GEMM2
    gemm_tile(As, Ws, acc, m_base, n_base, qid, tid4);

    // ---- epilogue
    const int rowA = m0 + m_base + qid;
    const int rowB = rowA + 8;
    if (do_pool) {
        int gA = g_batch[rowA];
        int gB = g_batch[rowB];
#pragma unroll
        for (int nt = 0; nt < 4; ++nt) {
            int col = n_base + nt * 8 + 2 * tid4;
            float2 bv = *(const float2*)&bb[col];
            float v0 = fmaxf(acc[nt][0] + bv.x, 0.f);
            float v1 = fmaxf(acc[nt][1] + bv.y, 0.f);
            float v2 = fmaxf(acc[nt][2] + bv.x, 0.f);
            float v3 = fmaxf(acc[nt][3] + bv.y, 0.f);
            if (gA == gB) {
                atomicAdd(&g_gsum[gA * C + col],     v0 + v2);
                atomicAdd(&g_gsum[gA * C + col + 1], v1 + v3);
            } else {
                atomicAdd(&g_gsum[gA * C + col],     v0);
                atomicAdd(&g_gsum[gA * C + col + 1], v1);
                atomicAdd(&g_gsum[gB * C + col],     v2);
                atomicAdd(&g_gsum[gB * C + col + 1], v3);
            }
        }
    } else {
        // store h1 as bf16 (next layer's gather source)
#pragma unroll
        for (int nt = 0; nt < 4; ++nt) {
            int col = n_base + nt * 8 + 2 * tid4;
            float2 bv = *(const float2*)&bb[col];
            __nv_bfloat162 pA = __float22bfloat162_rn(
                make_float2(fmaxf(acc[nt][0] + bv.x, 0.f), fmaxf(acc[nt][1] + bv.y, 0.f)));
            __nv_bfloat162 pB = __float22bfloat162_rn(
                make_float2(fmaxf(acc[nt][2] + bv.x, 0.f), fmaxf(acc[nt][3] + bv.y, 0.f)));
            *(__nv_bfloat162*)&outb[(size_t)rowA * C + col] = pA;
            *(__nv_bfloat162*)&outb[(size_t)rowB * C + col] = pB;
        }
    }
}

// ---------------- finalize: out[g] = (gsum[g]/cnt[g]) . fc_w + fc_b ----------------
__global__ void finalize_kernel(const float* __restrict__ fc_w,
                                const float* __restrict__ fc_b,
                                float* __restrict__ out) {
    int g = blockIdx.x;
    int t = threadIdx.x;  // 128
    float v = g_gsum[g * C + t] * fc_w[t];
#pragma unroll
    for (int o = 16; o > 0; o >>= 1) v += __shfl_down_sync(0xFFFFFFFFu, v, o);
    __shared__ float ws[4];
    if ((t & 31) == 0) ws[t >> 5] = v;
    __syncthreads();
    if (t == 0) {
        float s = ws[0] + ws[1] + ws[2] + ws[3];
        out[g] = s / fmaxf(g_gcnt[g], 1.0f) + fc_b[0];
    }
}

// ---------------- launch ----------------
extern "C" void kernel_launch(void* const* d_in, const int* in_sizes, int n_in,
                              void* d_out, int out_size) {
    const float* x    = (const float*)d_in[0];
    const void*  eidx = d_in[1];
    const void*  batv = d_in[2];
    const float* W1a  = (const float*)d_in[3];
    const float* b1a  = (const float*)d_in[4];
    const float* W1b  = (const float*)d_in[5];
    const float* b1b  = (const float*)d_in[6];
    const float* W2a  = (const float*)d_in[7];
    const float* b2a  = (const float*)d_in[8];
    const float* W2b  = (const float*)d_in[9];
    const float* b2b  = (const float*)d_in[10];
    const float* fcw  = (const float*)d_in[11];
    const float* fcb  = (const float*)d_in[12];
    float* out = (float*)d_out;
    (void)in_sizes; (void)n_in; (void)out_size;

    cudaFuncSetAttribute(fused_conv,
                         cudaFuncAttributeMaxDynamicSharedMemorySize, CONV_SMEM);

    float* p_Wt;
    __nv_bfloat16 *p_xb, *p_hb;
    cudaGetSymbolAddress((void**)&p_Wt, g_Wt);
    cudaGetSymbolAddress((void**)&p_xb, g_xb);
    cudaGetSymbolAddress((void**)&p_hb, g_hb);

    const int conv_blocks = N_NODES / TILE_ROWS;   // 625, exact

    // ---- setup + conversions + adjacency build (one pass, no scan)
    setup_kernel<<<(N_NODES + 255) / 256, 256>>>((const int*)eidx);
    preround_w<<<64, 256>>>(W1a, W1b, W2a, W2b);
    convert_x<<<(N_NODES * C / 8 + 255) / 256, 256>>>(x);
    build_adj<<<(N_EDGES / 4 + 255) / 256, 256>>>(eidx, batv);

    // ---- conv1 (fused gather + MLP, bf16 in/out)
    fused_conv<<<conv_blocks, 256, CONV_SMEM>>>(
        p_xb, p_Wt + 0 * C * C, b1a, p_Wt + 1 * C * C, b1b, p_hb, 0);
    // ---- conv2 (fused gather + MLP + pool)
    fused_conv<<<conv_blocks, 256, CONV_SMEM>>>(
        p_hb, p_Wt + 2 * C * C, b2a, p_Wt + 3 * C * C, b2b, nullptr, 1);

    finalize_kernel<<<NUM_GRAPHS, C>>>(fcw, fcb, out);
}

// round 11
// speedup vs baseline: 1.0045x; 1.0045x over previous
#include <cuda_runtime.h>
#include <cuda_bf16.h>
#include <cstdint>

#define N_NODES 20000
#define N_EDGES 640000
#define C 128
#define NUM_GRAPHS 64
#define CAP 128                        // bucket capacity per node (max deg ~58)

// ---------------- scratch (no allocations allowed) ----------------
__device__ __nv_bfloat16 g_xb[N_NODES * C];  // bf16 copy of x (gather source, layer 1)
__device__ __nv_bfloat16 g_hb[N_NODES * C];  // bf16 h1 (gather source, layer 2)
__device__ float g_Wt[4][C * C];       // tf32-pre-rounded W1a, W1b, W2a, W2b
__device__ float g_gsum[NUM_GRAPHS * C];
__device__ float g_gcnt[NUM_GRAPHS];
__device__ int   g_src[N_EDGES];
__device__ int   g_dst[N_EDGES];
__device__ int   g_rank[N_EDGES];      // within-dst arrival rank
__device__ int   g_csrc[N_NODES * CAP];// bucketed adjacency
__device__ int   g_deg[N_NODES];
__device__ int   g_batch[N_NODES];
__device__ int   g_is64;

// ---------------- helpers ----------------
__device__ __forceinline__ float tf32r(float x) {
    uint32_t u; asm("cvt.rna.tf32.f32 %0, %1;" : "=r"(u) : "f"(x));
    return __uint_as_float(u);
}
__device__ __forceinline__ void mma8(float* c, uint32_t a0, uint32_t a1, uint32_t a2,
                                     uint32_t a3, uint32_t b0, uint32_t b1) {
    asm volatile("mma.sync.aligned.m16n8k8.row.col.f32.tf32.tf32.f32 "
                 "{%0,%1,%2,%3}, {%4,%5,%6,%7}, {%8,%9}, {%0,%1,%2,%3};"
                 : "+f"(c[0]), "+f"(c[1]), "+f"(c[2]), "+f"(c[3])
                 : "r"(a0), "r"(a1), "r"(a2), "r"(a3), "r"(b0), "r"(b1));
}
// load 8 bf16 channels (16B) and add into f[8]
__device__ __forceinline__ void ld_bf8_add(const __nv_bfloat16* p, float* f) {
    uint4 u = *(const uint4*)p;
    __nv_bfloat162 h0 = *reinterpret_cast<__nv_bfloat162*>(&u.x);
    __nv_bfloat162 h1 = *reinterpret_cast<__nv_bfloat162*>(&u.y);
    __nv_bfloat162 h2 = *reinterpret_cast<__nv_bfloat162*>(&u.z);
    __nv_bfloat162 h3 = *reinterpret_cast<__nv_bfloat162*>(&u.w);
    float2 f0 = __bfloat1622float2(h0);
    float2 f1 = __bfloat1622float2(h1);
    float2 f2 = __bfloat1622float2(h2);
    float2 f3 = __bfloat1622float2(h3);
    f[0] += f0.x; f[1] += f0.y; f[2] += f1.x; f[3] += f1.y;
    f[4] += f2.x; f[5] += f2.y; f[6] += f3.x; f[7] += f3.y;
}

// ---------------- mega setup: zeros + dtype detect + W preround + x->bf16 ----------------
__global__ void mega_setup(const float* __restrict__ x,
                           const float* __restrict__ W1a, const float* __restrict__ W1b,
                           const float* __restrict__ W2a, const float* __restrict__ W2b,
                           const int* __restrict__ eidx_raw) {
    int i = blockIdx.x * blockDim.x + threadIdx.x;   // up to 320000
    if (i < N_NODES * C / 8) {                       // convert x (8 floats/thread)
        float4 a = ((const float4*)x)[i * 2];
        float4 b = ((const float4*)x)[i * 2 + 1];
        uint4 o;
        __nv_bfloat162 p0 = __float22bfloat162_rn(make_float2(a.x, a.y));
        __nv_bfloat162 p1 = __float22bfloat162_rn(make_float2(a.z, a.w));
        __nv_bfloat162 p2 = __float22bfloat162_rn(make_float2(b.x, b.y));
        __nv_bfloat162 p3 = __float22bfloat162_rn(make_float2(b.z, b.w));
        o.x = *reinterpret_cast<uint32_t*>(&p0);
        o.y = *reinterpret_cast<uint32_t*>(&p1);
        o.z = *reinterpret_cast<uint32_t*>(&p2);
        o.w = *reinterpret_cast<uint32_t*>(&p3);
        ((uint4*)g_xb)[i] = o;
    }
    if (i < 16384) {                                 // preround W (float4/thread)
        int which = i >> 12;
        int idx = i & 4095;
        const float* src = (which == 0) ? W1a : (which == 1) ? W1b
                         : (which == 2) ? W2a : W2b;
        float4 v = ((const float4*)src)[idx];
        ((float4*)g_Wt[which])[idx] =
            make_float4(tf32r(v.x), tf32r(v.y), tf32r(v.z), tf32r(v.w));
    }
    if (i < N_NODES) g_deg[i] = 0;
    if (i < NUM_GRAPHS * C) g_gsum[i] = 0.f;
    if (i < NUM_GRAPHS) g_gcnt[i] = 0.f;
    if (i == 0) {
        int any = 0;
#pragma unroll
        for (int k = 1; k < 128; k += 2) any |= eidx_raw[k];
        g_is64 = (any == 0) ? 1 : 0;
    }
}

// ---------------- convert indices + degree histogram (rank captured) ----------------
__global__ void convert_indices(const void* __restrict__ eidx,
                                const void* __restrict__ batch) {
    int i0 = (blockIdx.x * blockDim.x + threadIdx.x) * 4;
    if (g_is64) {
        const long long* e = (const long long*)eidx;
        if (i0 < N_EDGES) {
            longlong2 s01 = *(const longlong2*)&e[i0];
            longlong2 s23 = *(const longlong2*)&e[i0 + 2];
            longlong2 d01 = *(const longlong2*)&e[N_EDGES + i0];
            longlong2 d23 = *(const longlong2*)&e[N_EDGES + i0 + 2];
            int4 s = make_int4((int)s01.x, (int)s01.y, (int)s23.x, (int)s23.y);
            int4 d = make_int4((int)d01.x, (int)d01.y, (int)d23.x, (int)d23.y);
            *(int4*)&g_src[i0] = s;
            *(int4*)&g_dst[i0] = d;
            int4 r;
            r.x = atomicAdd(&g_deg[d.x], 1);
            r.y = atomicAdd(&g_deg[d.y], 1);
            r.z = atomicAdd(&g_deg[d.z], 1);
            r.w = atomicAdd(&g_deg[d.w], 1);
            *(int4*)&g_rank[i0] = r;
        }
        if (i0 < N_NODES) {
            const long long* b = (const long long*)batch;
            longlong2 b01 = *(const longlong2*)&b[i0];
            longlong2 b23 = *(const longlong2*)&b[i0 + 2];
            int4 g = make_int4((int)b01.x, (int)b01.y, (int)b23.x, (int)b23.y);
            *(int4*)&g_batch[i0] = g;
            atomicAdd(&g_gcnt[g.x], 1.f); atomicAdd(&g_gcnt[g.y], 1.f);
            atomicAdd(&g_gcnt[g.z], 1.f); atomicAdd(&g_gcnt[g.w], 1.f);
        }
    } else {
        const int* e = (const int*)eidx;
        if (i0 < N_EDGES) {
            int4 s = *(const int4*)&e[i0];
            int4 d = *(const int4*)&e[N_EDGES + i0];
            *(int4*)&g_src[i0] = s;
            *(int4*)&g_dst[i0] = d;
            int4 r;
            r.x = atomicAdd(&g_deg[d.x], 1);
            r.y = atomicAdd(&g_deg[d.y], 1);
            r.z = atomicAdd(&g_deg[d.z], 1);
            r.w = atomicAdd(&g_deg[d.w], 1);
            *(int4*)&g_rank[i0] = r;
        }
        if (i0 < N_NODES) {
            int4 g = *(const int4*)&((const int*)batch)[i0];
            *(int4*)&g_batch[i0] = g;
            atomicAdd(&g_gcnt[g.x], 1.f); atomicAdd(&g_gcnt[g.y], 1.f);
            atomicAdd(&g_gcnt[g.z], 1.f); atomicAdd(&g_gcnt[g.w], 1.f);
        }
    }
}

// ---------------- bucket fill: pos = dst*CAP + rank (atomic-free) ----------------
__global__ void fill_csr() {
    int i0 = (blockIdx.x * blockDim.x + threadIdx.x) * 4;
    if (i0 + 3 < N_EDGES) {
        int4 d = *(const int4*)&g_dst[i0];
        int4 s = *(const int4*)&g_src[i0];
        int4 r = *(const int4*)&g_rank[i0];
        if (r.x < CAP) g_csrc[d.x * CAP + r.x] = s.x;
        if (r.y < CAP) g_csrc[d.y * CAP + r.y] = s.y;
        if (r.z < CAP) g_csrc[d.z * CAP + r.z] = s.z;
        if (r.w < CAP) g_csrc[d.w * CAP + r.w] = s.w;
    } else {
        for (int i = i0; i < N_EDGES; ++i) {
            int r = g_rank[i];
            if (r < CAP) g_csrc[g_dst[i] * CAP + r] = g_src[i];
        }
    }
}

// ---------------- fused conv layer ----------------
#define TILE_ROWS 32
#define ASTR 132
#define WSTR 136
#define CONV_SMEM ((128 * WSTR + TILE_ROWS * ASTR) * 4)

__device__ __forceinline__ void gemm_tile(const float* __restrict__ As,
                                          const float* __restrict__ Ws,
                                          float acc[4][4],
                                          int m_base, int n_base, int qid, int tid4)
{
#pragma unroll
    for (int nt = 0; nt < 4; ++nt)
#pragma unroll
        for (int j = 0; j < 4; ++j) acc[nt][j] = 0.f;

#pragma unroll
    for (int k0 = 0; k0 < 128; k0 += 8) {
        const float* ar0 = &As[(m_base + qid) * ASTR + k0 + tid4];
        const float* ar1 = &As[(m_base + qid + 8) * ASTR + k0 + tid4];
        uint32_t a0 = __float_as_uint(ar0[0]);
        uint32_t a1 = __float_as_uint(ar1[0]);
        uint32_t a2 = __float_as_uint(ar0[4]);
        uint32_t a3 = __float_as_uint(ar1[4]);
        const float* wr0 = &Ws[(k0 + tid4) * WSTR + n_base + qid];
        const float* wr1 = wr0 + 4 * WSTR;
#pragma unroll
        for (int nt = 0; nt < 4; ++nt) {
            uint32_t b0 = __float_as_uint(wr0[nt * 8]);
            uint32_t b1 = __float_as_uint(wr1[nt * 8]);
            mma8(acc[nt], a0, a1, a2, a3, b0, b1);
        }
    }
}

__global__ void __launch_bounds__(256, 2) fused_conv(
    const __nv_bfloat16* __restrict__ feat,
    const float* __restrict__ Wa, const float* __restrict__ ba,
    const float* __restrict__ Wb, const float* __restrict__ bb,
    __nv_bfloat16* __restrict__ outb, int do_pool)
{
    extern __shared__ float sm[];
    float* Ws = sm;                       // [128][WSTR]
    float* As = sm + 128 * WSTR;          // [32][ASTR]

    const int t = threadIdx.x;
    const int m0 = blockIdx.x * TILE_ROWS;
    const int lane = t & 31;
    const int w = t >> 5;

    // ---- load Wa (tf32-pre-rounded): pure float4 copy
#pragma unroll
    for (int i = 0; i < 16; ++i) {
        int idx = t + i * 256;
        float4 v = ((const float4*)Wa)[idx];
        int kk = idx >> 5;
        int nn = (idx & 31) * 4;
        *(float4*)&Ws[kk * WSTR + nn] = v;
    }

    // ---- gather: warp per node, 4 nodes/warp; PAIRED edges:
    // lanes 0-15 handle edge e, lanes 16-31 edge e+1; each lane loads 8 bf16
    // channels (16B = LDG.128), so one instruction covers 2 edges.
    const int half = lane >> 4;           // 0 or 1
    const int hl = lane & 15;             // channel chunk: cols hl*8..+7
    const int chb = hl * 8;
#pragma unroll
    for (int i = 0; i < 4; ++i) {
        int r = w * 4 + i;
        int node = m0 + r;
        float av[8];
#pragma unroll
        for (int j = 0; j < 8; ++j) av[j] = 0.f;
        if (half == 0)                    // self term (GIN eps=0)
            ld_bf8_add(&feat[(size_t)node * C + chb], av);
        const int* adj = &g_csrc[node * CAP];
        int deg = g_deg[node];
        if (deg > CAP) deg = CAP;
        int e = 0;
        for (; e + 8 <= deg; e += 8) {    // 4 pairs per iteration (MLP 4)
            int s0 = adj[e + half];
            int s1 = adj[e + 2 + half];
            int s2 = adj[e + 4 + half];
            int s3 = adj[e + 6 + half];
            ld_bf8_add(&feat[(size_t)s0 * C + chb], av);
            ld_bf8_add(&feat[(size_t)s1 * C + chb], av);
            ld_bf8_add(&feat[(size_t)s2 * C + chb], av);
            ld_bf8_add(&feat[(size_t)s3 * C + chb], av);
        }
        for (; e + 2 <= deg; e += 2) {
            int s = adj[e + half];
            ld_bf8_add(&feat[(size_t)s * C + chb], av);
        }
        if (e < deg && half == 0) {       // odd tail
            ld_bf8_add(&feat[(size_t)adj[e] * C + chb], av);
        }
        // combine halves
#pragma unroll
        for (int j = 0; j < 8; ++j)
            av[j] += __shfl_xor_sync(0xFFFFFFFFu, av[j], 16);
        // write: half 0 -> cols chb..+3, half 1 -> cols chb+4..+7
        float4 o = (half == 0)
            ? make_float4(tf32r(av[0]), tf32r(av[1]), tf32r(av[2]), tf32r(av[3]))
            : make_float4(tf32r(av[4]), tf32r(av[5]), tf32r(av[6]), tf32r(av[7]));
        *(float4*)&As[r * ASTR + chb + half * 4] = o;
    }
    __syncthreads();

    const int warp_m = w & 1;
    const int warp_n = w >> 1;
    const int m_base = warp_m * 16;
    const int n_base = warp_n * 32;
    const int qid = lane >> 2;
    const int tid4 = lane & 3;

    float acc[4][4];

    // ---- GEMM1
    gemm_tile(As, Ws, acc, m_base, n_base, qid, tid4);
    __syncthreads();

    // ---- t = tf32(relu(acc + ba)) -> As ; reload Ws with Wb
#pragma unroll
    for (int nt = 0; nt < 4; ++nt) {
        int col = n_base + nt * 8 + 2 * tid4;
        float2 bv = *(const float2*)&ba[col];
        int r0 = m_base + qid, r1 = r0 + 8;
        *(float2*)&As[r0 * ASTR + col] =
            make_float2(tf32r(fmaxf(acc[nt][0] + bv.x, 0.f)),
                        tf32r(fmaxf(acc[nt][1] + bv.y, 0.f)));
        *(float2*)&As[r1 * ASTR + col] =
            make_float2(tf32r(fmaxf(acc[nt][2] + bv.x, 0.f)),
                        tf32r(fmaxf(acc[nt][3] + bv.y, 0.f)));
    }
#pragma unroll
    for (int i = 0; i < 16; ++i) {
        int idx = t + i * 256;
        float4 v = ((const float4*)Wb)[idx];
        int kk = idx >> 5;
        int nn = (idx & 31) * 4;
        *(float4*)&Ws[kk * WSTR + nn] = v;
    }
    __syncthreads();

    // ---- GEMM2
    gemm_tile(As, Ws, acc, m_base, n_base, qid, tid4);

    // ---- epilogue
    const int rowA = m0 + m_base + qid;
    const int rowB = rowA + 8;
    if (do_pool) {
        int gA = g_batch[rowA];
        int gB = g_batch[rowB];
#pragma unroll
        for (int nt = 0; nt < 4; ++nt) {
            int col = n_base + nt * 8 + 2 * tid4;
            float2 bv = *(const float2*)&bb[col];
            float v0 = fmaxf(acc[nt][0] + bv.x, 0.f);
            float v1 = fmaxf(acc[nt][1] + bv.y, 0.f);
            float v2 = fmaxf(acc[nt][2] + bv.x, 0.f);
            float v3 = fmaxf(acc[nt][3] + bv.y, 0.f);
            if (gA == gB) {
                atomicAdd(&g_gsum[gA * C + col],     v0 + v2);
                atomicAdd(&g_gsum[gA * C + col + 1], v1 + v3);
            } else {
                atomicAdd(&g_gsum[gA * C + col],     v0);
                atomicAdd(&g_gsum[gA * C + col + 1], v1);
                atomicAdd(&g_gsum[gB * C + col],     v2);
                atomicAdd(&g_gsum[gB * C + col + 1], v3);
            }
        }
    } else {
#pragma unroll
        for (int nt = 0; nt < 4; ++nt) {
            int col = n_base + nt * 8 + 2 * tid4;
            float2 bv = *(const float2*)&bb[col];
            __nv_bfloat162 pA = __float22bfloat162_rn(
                make_float2(fmaxf(acc[nt][0] + bv.x, 0.f), fmaxf(acc[nt][1] + bv.y, 0.f)));
            __nv_bfloat162 pB = __float22bfloat162_rn(
                make_float2(fmaxf(acc[nt][2] + bv.x, 0.f), fmaxf(acc[nt][3] + bv.y, 0.f)));
            *(__nv_bfloat162*)&outb[(size_t)rowA * C + col] = pA;
            *(__nv_bfloat162*)&outb[(size_t)rowB * C + col] = pB;
        }
    }
}

// ---------------- finalize ----------------
__global__ void finalize_kernel(const float* __restrict__ fc_w,
                                const float* __restrict__ fc_b,
                                float* __restrict__ out) {
    int g = blockIdx.x;
    int t = threadIdx.x;  // 128
    float v = g_gsum[g * C + t] * fc_w[t];
#pragma unroll
    for (int o = 16; o > 0; o >>= 1) v += __shfl_down_sync(0xFFFFFFFFu, v, o);
    __shared__ float ws[4];
    if ((t & 31) == 0) ws[t >> 5] = v;
    __syncthreads();
    if (t == 0) {
        float s = ws[0] + ws[1] + ws[2] + ws[3];
        out[g] = s / fmaxf(g_gcnt[g], 1.0f) + fc_b[0];
    }
}

// ---------------- launch ----------------
extern "C" void kernel_launch(void* const* d_in, const int* in_sizes, int n_in,
                              void* d_out, int out_size) {
    const float* x    = (const float*)d_in[0];
    const void*  eidx = d_in[1];
    const void*  batv = d_in[2];
    const float* W1a  = (const float*)d_in[3];
    const float* b1a  = (const float*)d_in[4];
    const float* W1b  = (const float*)d_in[5];
    const float* b1b  = (const float*)d_in[6];
    const float* W2a  = (const float*)d_in[7];
    const float* b2a  = (const float*)d_in[8];
    const float* W2b  = (const float*)d_in[9];
    const float* b2b  = (const float*)d_in[10];
    const float* fcw  = (const float*)d_in[11];
    const float* fcb  = (const float*)d_in[12];
    float* out = (float*)d_out;
    (void)in_sizes; (void)n_in; (void)out_size;

    cudaFuncSetAttribute(fused_conv,
                         cudaFuncAttributeMaxDynamicSharedMemorySize, CONV_SMEM);

    float* p_Wt;
    __nv_bfloat16 *p_xb, *p_hb;
    cudaGetSymbolAddress((void**)&p_Wt, g_Wt);
    cudaGetSymbolAddress((void**)&p_xb, g_xb);
    cudaGetSymbolAddress((void**)&p_hb, g_hb);

    const int conv_blocks = N_NODES / TILE_ROWS;   // 625, exact

    // #1: setup + W preround + x->bf16 (one elementwise kernel)
    mega_setup<<<(N_NODES * C / 8 + 255) / 256, 256>>>(
        x, W1a, W1b, W2a, W2b, (const int*)eidx);
    // #2: index convert + degree histogram (rank capture)
    convert_indices<<<(N_EDGES / 4 + 255) / 256, 256>>>(eidx, batv);
    // #3: bucket fill (atomic-free)
    fill_csr<<<(N_EDGES / 4 + 255) / 256, 256>>>();
    // #4 (ncu-profiled): conv1
    fused_conv<<<conv_blocks, 256, CONV_SMEM>>>(
        p_xb, p_Wt + 0 * C * C, b1a, p_Wt + 1 * C * C, b1b, p_hb, 0);
    // #5: conv2 (+ fused pool)
    fused_conv<<<conv_blocks, 256, CONV_SMEM>>>(
        p_hb, p_Wt + 2 * C * C, b2a, p_Wt + 3 * C * C, b2b, nullptr, 1);
    // #6: finalize
    finalize_kernel<<<NUM_GRAPHS, C>>>(fcw, fcb, out);
}

// round 12
// speedup vs baseline: 1.1615x; 1.1563x over previous
#include <cuda_runtime.h>
#include <cuda_bf16.h>
#include <cstdint>

#define N_NODES 20000
#define N_EDGES 640000
#define C 128
#define NUM_GRAPHS 64
#define CAP 128                        // bucket capacity per node (max deg ~58)

// ---------------- scratch (no allocations allowed) ----------------
__device__ __nv_bfloat16 g_xb[N_NODES * C];  // bf16 x (gather source, layer 1)
__device__ __nv_bfloat16 g_hb[N_NODES * C];  // bf16 h1 (gather source, layer 2)
__device__ float g_agg[N_NODES * C];         // tf32-rounded gather output
__device__ float g_Wt[4][C * C];       // tf32-pre-rounded W1a, W1b, W2a, W2b
__device__ float g_gsum[NUM_GRAPHS * C];
__device__ float g_gcnt[NUM_GRAPHS];
__device__ int   g_src[N_EDGES];
__device__ int   g_dst[N_EDGES];
__device__ int   g_rank[N_EDGES];
__device__ int   g_csrc[N_NODES * CAP];
__device__ int   g_deg[N_NODES];
__device__ int   g_batch[N_NODES];
__device__ int   g_is64;

// ---------------- helpers ----------------
__device__ __forceinline__ float tf32r(float x) {
    uint32_t u; asm("cvt.rna.tf32.f32 %0, %1;" : "=r"(u) : "f"(x));
    return __uint_as_float(u);
}
__device__ __forceinline__ void mma8(float* c, uint32_t a0, uint32_t a1, uint32_t a2,
                                     uint32_t a3, uint32_t b0, uint32_t b1) {
    asm volatile("mma.sync.aligned.m16n8k8.row.col.f32.tf32.tf32.f32 "
                 "{%0,%1,%2,%3}, {%4,%5,%6,%7}, {%8,%9}, {%0,%1,%2,%3};"
                 : "+f"(c[0]), "+f"(c[1]), "+f"(c[2]), "+f"(c[3])
                 : "r"(a0), "r"(a1), "r"(a2), "r"(a3), "r"(b0), "r"(b1));
}
__device__ __forceinline__ void ld_bf8_add(const __nv_bfloat16* p, float* f) {
    uint4 u = *(const uint4*)p;
    __nv_bfloat162 h0 = *reinterpret_cast<__nv_bfloat162*>(&u.x);
    __nv_bfloat162 h1 = *reinterpret_cast<__nv_bfloat162*>(&u.y);
    __nv_bfloat162 h2 = *reinterpret_cast<__nv_bfloat162*>(&u.z);
    __nv_bfloat162 h3 = *reinterpret_cast<__nv_bfloat162*>(&u.w);
    float2 f0 = __bfloat1622float2(h0);
    float2 f1 = __bfloat1622float2(h1);
    float2 f2 = __bfloat1622float2(h2);
    float2 f3 = __bfloat1622float2(h3);
    f[0] += f0.x; f[1] += f0.y; f[2] += f1.x; f[3] += f1.y;
    f[4] += f2.x; f[5] += f2.y; f[6] += f3.x; f[7] += f3.y;
}

// ---------------- mega setup ----------------
__global__ void mega_setup(const float* __restrict__ x,
                           const float* __restrict__ W1a, const float* __restrict__ W1b,
                           const float* __restrict__ W2a, const float* __restrict__ W2b,
                           const int* __restrict__ eidx_raw) {
    int i = blockIdx.x * blockDim.x + threadIdx.x;
    if (i < N_NODES * C / 8) {
        float4 a = ((const float4*)x)[i * 2];
        float4 b = ((const float4*)x)[i * 2 + 1];
        uint4 o;
        __nv_bfloat162 p0 = __float22bfloat162_rn(make_float2(a.x, a.y));
        __nv_bfloat162 p1 = __float22bfloat162_rn(make_float2(a.z, a.w));
        __nv_bfloat162 p2 = __float22bfloat162_rn(make_float2(b.x, b.y));
        __nv_bfloat162 p3 = __float22bfloat162_rn(make_float2(b.z, b.w));
        o.x = *reinterpret_cast<uint32_t*>(&p0);
        o.y = *reinterpret_cast<uint32_t*>(&p1);
        o.z = *reinterpret_cast<uint32_t*>(&p2);
        o.w = *reinterpret_cast<uint32_t*>(&p3);
        ((uint4*)g_xb)[i] = o;
    }
    if (i < 16384) {
        int which = i >> 12;
        int idx = i & 4095;
        const float* src = (which == 0) ? W1a : (which == 1) ? W1b
                         : (which == 2) ? W2a : W2b;
        float4 v = ((const float4*)src)[idx];
        ((float4*)g_Wt[which])[idx] =
            make_float4(tf32r(v.x), tf32r(v.y), tf32r(v.z), tf32r(v.w));
    }
    if (i < N_NODES) g_deg[i] = 0;
    if (i < NUM_GRAPHS * C) g_gsum[i] = 0.f;
    if (i < NUM_GRAPHS) g_gcnt[i] = 0.f;
    if (i == 0) {
        int any = 0;
#pragma unroll
        for (int k = 1; k < 128; k += 2) any |= eidx_raw[k];
        g_is64 = (any == 0) ? 1 : 0;
    }
}

// ---------------- convert indices + degree histogram ----------------
__global__ void convert_indices(const void* __restrict__ eidx,
                                const void* __restrict__ batch) {
    int i0 = (blockIdx.x * blockDim.x + threadIdx.x) * 4;
    if (g_is64) {
        const long long* e = (const long long*)eidx;
        if (i0 < N_EDGES) {
            longlong2 s01 = *(const longlong2*)&e[i0];
            longlong2 s23 = *(const longlong2*)&e[i0 + 2];
            longlong2 d01 = *(const longlong2*)&e[N_EDGES + i0];
            longlong2 d23 = *(const longlong2*)&e[N_EDGES + i0 + 2];
            int4 s = make_int4((int)s01.x, (int)s01.y, (int)s23.x, (int)s23.y);
            int4 d = make_int4((int)d01.x, (int)d01.y, (int)d23.x, (int)d23.y);
            *(int4*)&g_src[i0] = s;
            *(int4*)&g_dst[i0] = d;
            int4 r;
            r.x = atomicAdd(&g_deg[d.x], 1);
            r.y = atomicAdd(&g_deg[d.y], 1);
            r.z = atomicAdd(&g_deg[d.z], 1);
            r.w = atomicAdd(&g_deg[d.w], 1);
            *(int4*)&g_rank[i0] = r;
        }
        if (i0 < N_NODES) {
            const long long* b = (const long long*)batch;
            longlong2 b01 = *(const longlong2*)&b[i0];
            longlong2 b23 = *(const longlong2*)&b[i0 + 2];
            int4 g = make_int4((int)b01.x, (int)b01.y, (int)b23.x, (int)b23.y);
            *(int4*)&g_batch[i0] = g;
            atomicAdd(&g_gcnt[g.x], 1.f); atomicAdd(&g_gcnt[g.y], 1.f);
            atomicAdd(&g_gcnt[g.z], 1.f); atomicAdd(&g_gcnt[g.w], 1.f);
        }
    } else {
        const int* e = (const int*)eidx;
        if (i0 < N_EDGES) {
            int4 s = *(const int4*)&e[i0];
            int4 d = *(const int4*)&e[N_EDGES + i0];
            *(int4*)&g_src[i0] = s;
            *(int4*)&g_dst[i0] = d;
            int4 r;
            r.x = atomicAdd(&g_deg[d.x], 1);
            r.y = atomicAdd(&g_deg[d.y], 1);
            r.z = atomicAdd(&g_deg[d.z], 1);
            r.w = atomicAdd(&g_deg[d.w], 1);
            *(int4*)&g_rank[i0] = r;
        }
        if (i0 < N_NODES) {
            int4 g = *(const int4*)&((const int*)batch)[i0];
            *(int4*)&g_batch[i0] = g;
            atomicAdd(&g_gcnt[g.x], 1.f); atomicAdd(&g_gcnt[g.y], 1.f);
            atomicAdd(&g_gcnt[g.z], 1.f); atomicAdd(&g_gcnt[g.w], 1.f);
        }
    }
}

// ---------------- bucket fill (atomic-free) ----------------
__global__ void fill_csr() {
    int i0 = (blockIdx.x * blockDim.x + threadIdx.x) * 4;
    if (i0 + 3 < N_EDGES) {
        int4 d = *(const int4*)&g_dst[i0];
        int4 s = *(const int4*)&g_src[i0];
        int4 r = *(const int4*)&g_rank[i0];
        if (r.x < CAP) g_csrc[d.x * CAP + r.x] = s.x;
        if (r.y < CAP) g_csrc[d.y * CAP + r.y] = s.y;
        if (r.z < CAP) g_csrc[d.z * CAP + r.z] = s.z;
        if (r.w < CAP) g_csrc[d.w * CAP + r.w] = s.w;
    } else {
        for (int i = i0; i < N_EDGES; ++i) {
            int r = g_rank[i];
            if (r < CAP) g_csrc[g_dst[i] * CAP + r] = g_src[i];
        }
    }
}

// ---------------- standalone gather: high-occupancy, no smem ----------------
// warp per node (4 nodes/warp); paired edges: half-warps handle alternating
// edges with LDG.128 (8 bf16 channels/lane). Output: tf32-rounded fp32 agg.
__global__ void __launch_bounds__(256) gather_kernel(
    const __nv_bfloat16* __restrict__ feat, float* __restrict__ agg)
{
    const int t = threadIdx.x;
    const int lane = t & 31;
    const int w = t >> 5;
    const int half = lane >> 4;           // 0 or 1
    const int chb = (lane & 15) * 8;      // channel base
#pragma unroll
    for (int i = 0; i < 4; ++i) {
        int node = blockIdx.x * 32 + w * 4 + i;   // grid 625 -> exact
        float av[8];
#pragma unroll
        for (int j = 0; j < 8; ++j) av[j] = 0.f;
        if (half == 0)                    // self term (GIN eps=0)
            ld_bf8_add(&feat[(size_t)node * C + chb], av);
        const int* adj = &g_csrc[node * CAP];
        int deg = g_deg[node];
        if (deg > CAP) deg = CAP;
        int e = 0;
        for (; e + 8 <= deg; e += 8) {
            int s0 = adj[e + half];
            int s1 = adj[e + 2 + half];
            int s2 = adj[e + 4 + half];
            int s3 = adj[e + 6 + half];
            ld_bf8_add(&feat[(size_t)s0 * C + chb], av);
            ld_bf8_add(&feat[(size_t)s1 * C + chb], av);
            ld_bf8_add(&feat[(size_t)s2 * C + chb], av);
            ld_bf8_add(&feat[(size_t)s3 * C + chb], av);
        }
        for (; e + 2 <= deg; e += 2) {
            int s = adj[e + half];
            ld_bf8_add(&feat[(size_t)s * C + chb], av);
        }
        if (e < deg && half == 0)
            ld_bf8_add(&feat[(size_t)adj[e] * C + chb], av);
#pragma unroll
        for (int j = 0; j < 8; ++j)
            av[j] += __shfl_xor_sync(0xFFFFFFFFu, av[j], 16);
        float4 o = (half == 0)
            ? make_float4(tf32r(av[0]), tf32r(av[1]), tf32r(av[2]), tf32r(av[3]))
            : make_float4(tf32r(av[4]), tf32r(av[5]), tf32r(av[6]), tf32r(av[7]));
        *(float4*)&agg[(size_t)node * C + chb + half * 4] = o;
    }
}

// ---------------- MLP kernel: GEMM1 + ReLU + GEMM2 (+pool) ----------------
#define TILE_ROWS 32
#define ASTR 132
#define WSTR 136
#define CONV_SMEM ((128 * WSTR + TILE_ROWS * ASTR) * 4)

__device__ __forceinline__ void gemm_tile(const float* __restrict__ As,
                                          const float* __restrict__ Ws,
                                          float acc[4][4],
                                          int m_base, int n_base, int qid, int tid4)
{
#pragma unroll
    for (int nt = 0; nt < 4; ++nt)
#pragma unroll
        for (int j = 0; j < 4; ++j) acc[nt][j] = 0.f;

#pragma unroll
    for (int k0 = 0; k0 < 128; k0 += 8) {
        const float* ar0 = &As[(m_base + qid) * ASTR + k0 + tid4];
        const float* ar1 = &As[(m_base + qid + 8) * ASTR + k0 + tid4];
        uint32_t a0 = __float_as_uint(ar0[0]);
        uint32_t a1 = __float_as_uint(ar1[0]);
        uint32_t a2 = __float_as_uint(ar0[4]);
        uint32_t a3 = __float_as_uint(ar1[4]);
        const float* wr0 = &Ws[(k0 + tid4) * WSTR + n_base + qid];
        const float* wr1 = wr0 + 4 * WSTR;
#pragma unroll
        for (int nt = 0; nt < 4; ++nt) {
            uint32_t b0 = __float_as_uint(wr0[nt * 8]);
            uint32_t b1 = __float_as_uint(wr1[nt * 8]);
            mma8(acc[nt], a0, a1, a2, a3, b0, b1);
        }
    }
}

__global__ void __launch_bounds__(256, 2) mlp_kernel(
    const float* __restrict__ agg,
    const float* __restrict__ Wa, const float* __restrict__ ba,
    const float* __restrict__ Wb, const float* __restrict__ bb,
    __nv_bfloat16* __restrict__ outb, int do_pool)
{
    extern __shared__ float sm[];
    float* Ws = sm;                       // [128][WSTR]
    float* As = sm + 128 * WSTR;          // [32][ASTR]

    const int t = threadIdx.x;
    const int m0 = blockIdx.x * TILE_ROWS;
    const int lane = t & 31;
    const int w = t >> 5;

    // load Wa (pure copy, pre-rounded)
#pragma unroll
    for (int i = 0; i < 16; ++i) {
        int idx = t + i * 256;
        float4 v = ((const float4*)Wa)[idx];
        *(float4*)&Ws[(idx >> 5) * WSTR + (idx & 31) * 4] = v;
    }
    // load A tile (coalesced; already tf32-rounded)
#pragma unroll
    for (int i = 0; i < 4; ++i) {
        int idx = t + i * 256;            // 1024 float4
        int r = idx >> 5;
        int c4 = idx & 31;
        float4 v = ((const float4*)agg)[(size_t)(m0 + r) * 32 + c4];
        *(float4*)&As[r * ASTR + c4 * 4] = v;
    }
    __syncthreads();

    const int warp_m = w & 1;
    const int warp_n = w >> 1;
    const int m_base = warp_m * 16;
    const int n_base = warp_n * 32;
    const int qid = lane >> 2;
    const int tid4 = lane & 3;

    float acc[4][4];

    // GEMM1
    gemm_tile(As, Ws, acc, m_base, n_base, qid, tid4);
    __syncthreads();

    // t = tf32(relu(acc + ba)) -> As ; reload Ws with Wb
#pragma unroll
    for (int nt = 0; nt < 4; ++nt) {
        int col = n_base + nt * 8 + 2 * tid4;
        float2 bv = *(const float2*)&ba[col];
        int r0 = m_base + qid, r1 = r0 + 8;
        *(float2*)&As[r0 * ASTR + col] =
            make_float2(tf32r(fmaxf(acc[nt][0] + bv.x, 0.f)),
                        tf32r(fmaxf(acc[nt][1] + bv.y, 0.f)));
        *(float2*)&As[r1 * ASTR + col] =
            make_float2(tf32r(fmaxf(acc[nt][2] + bv.x, 0.f)),
                        tf32r(fmaxf(acc[nt][3] + bv.y, 0.f)));
    }
#pragma unroll
    for (int i = 0; i < 16; ++i) {
        int idx = t + i * 256;
        float4 v = ((const float4*)Wb)[idx];
        *(float4*)&Ws[(idx >> 5) * WSTR + (idx & 31) * 4] = v;
    }
    __syncthreads();

    // GEMM2
    gemm_tile(As, Ws, acc, m_base, n_base, qid, tid4);

    // epilogue
    const int rowA = m0 + m_base + qid;
    const int rowB = rowA + 8;
    if (do_pool) {
        int gA = g_batch[rowA];
        int gB = g_batch[rowB];
#pragma unroll
        for (int nt = 0; nt < 4; ++nt) {
            int col = n_base + nt * 8 + 2 * tid4;
            float2 bv = *(const float2*)&bb[col];
            float v0 = fmaxf(acc[nt][0] + bv.x, 0.f);
            float v1 = fmaxf(acc[nt][1] + bv.y, 0.f);
            float v2 = fmaxf(acc[nt][2] + bv.x, 0.f);
            float v3 = fmaxf(acc[nt][3] + bv.y, 0.f);
            if (gA == gB) {
                atomicAdd(&g_gsum[gA * C + col],     v0 + v2);
                atomicAdd(&g_gsum[gA * C + col + 1], v1 + v3);
            } else {
                atomicAdd(&g_gsum[gA * C + col],     v0);
                atomicAdd(&g_gsum[gA * C + col + 1], v1);
                atomicAdd(&g_gsum[gB * C + col],     v2);
                atomicAdd(&g_gsum[gB * C + col + 1], v3);
            }
        }
    } else {
#pragma unroll
        for (int nt = 0; nt < 4; ++nt) {
            int col = n_base + nt * 8 + 2 * tid4;
            float2 bv = *(const float2*)&bb[col];
            __nv_bfloat162 pA = __float22bfloat162_rn(
                make_float2(fmaxf(acc[nt][0] + bv.x, 0.f), fmaxf(acc[nt][1] + bv.y, 0.f)));
            __nv_bfloat162 pB = __float22bfloat162_rn(
                make_float2(fmaxf(acc[nt][2] + bv.x, 0.f), fmaxf(acc[nt][3] + bv.y, 0.f)));
            *(__nv_bfloat162*)&outb[(size_t)rowA * C + col] = pA;
            *(__nv_bfloat162*)&outb[(size_t)rowB * C + col] = pB;
        }
    }
}

// ---------------- finalize ----------------
__global__ void finalize_kernel(const float* __restrict__ fc_w,
                                const float* __restrict__ fc_b,
                                float* __restrict__ out) {
    int g = blockIdx.x;
    int t = threadIdx.x;  // 128
    float v = g_gsum[g * C + t] * fc_w[t];
#pragma unroll
    for (int o = 16; o > 0; o >>= 1) v += __shfl_down_sync(0xFFFFFFFFu, v, o);
    __shared__ float ws[4];
    if ((t & 31) == 0) ws[t >> 5] = v;
    __syncthreads();
    if (t == 0) {
        float s = ws[0] + ws[1] + ws[2] + ws[3];
        out[g] = s / fmaxf(g_gcnt[g], 1.0f) + fc_b[0];
    }
}

// ---------------- launch ----------------
extern "C" void kernel_launch(void* const* d_in, const int* in_sizes, int n_in,
                              void* d_out, int out_size) {
    const float* x    = (const float*)d_in[0];
    const void*  eidx = d_in[1];
    const void*  batv = d_in[2];
    const float* W1a  = (const float*)d_in[3];
    const float* b1a  = (const float*)d_in[4];
    const float* W1b  = (const float*)d_in[5];
    const float* b1b  = (const float*)d_in[6];
    const float* W2a  = (const float*)d_in[7];
    const float* b2a  = (const float*)d_in[8];
    const float* W2b  = (const float*)d_in[9];
    const float* b2b  = (const float*)d_in[10];
    const float* fcw  = (const float*)d_in[11];
    const float* fcb  = (const float*)d_in[12];
    float* out = (float*)d_out;
    (void)in_sizes; (void)n_in; (void)out_size;

    cudaFuncSetAttribute(mlp_kernel,
                         cudaFuncAttributeMaxDynamicSharedMemorySize, CONV_SMEM);

    float *p_Wt, *p_agg;
    __nv_bfloat16 *p_xb, *p_hb;
    cudaGetSymbolAddress((void**)&p_Wt,  g_Wt);
    cudaGetSymbolAddress((void**)&p_agg, g_agg);
    cudaGetSymbolAddress((void**)&p_xb,  g_xb);
    cudaGetSymbolAddress((void**)&p_hb,  g_hb);

    const int conv_blocks = N_NODES / TILE_ROWS;   // 625, exact

    // #1: setup + W preround + x->bf16
    mega_setup<<<(N_NODES * C / 8 + 255) / 256, 256>>>(
        x, W1a, W1b, W2a, W2b, (const int*)eidx);
    // #2: index convert + degree histogram
    convert_indices<<<(N_EDGES / 4 + 255) / 256, 256>>>(eidx, batv);
    // #3: bucket fill
    fill_csr<<<(N_EDGES / 4 + 255) / 256, 256>>>();
    // #4 (ncu-profiled): gather layer 1
    gather_kernel<<<conv_blocks, 256>>>(p_xb, p_agg);
    // #5: MLP layer 1 -> h1 (bf16)
    mlp_kernel<<<conv_blocks, 256, CONV_SMEM>>>(
        p_agg, p_Wt + 0 * C * C, b1a, p_Wt + 1 * C * C, b1b, p_hb, 0);
    // #6: gather layer 2
    gather_kernel<<<conv_blocks, 256>>>(p_hb, p_agg);
    // #7: MLP layer 2 (+ fused pool)
    mlp_kernel<<<conv_blocks, 256, CONV_SMEM>>>(
        p_agg, p_Wt + 2 * C * C, b2a, p_Wt + 3 * C * C, b2b, nullptr, 1);
    // #8: finalize
    finalize_kernel<<<NUM_GRAPHS, C>>>(fcw, fcb, out);
}

// round 13
// speedup vs baseline: 1.2522x; 1.0781x over previous
#include <cuda_runtime.h>
#include <cuda_bf16.h>
#include <cstdint>

#define N_NODES 20000
#define N_EDGES 640000
#define C 128
#define NUM_GRAPHS 64
#define CAP 128                        // bucket capacity per node (max deg ~58)

// ---------------- scratch (no allocations allowed) ----------------
__device__ __nv_bfloat16 g_xb[N_NODES * C];  // bf16 x (gather source, layer 1)
__device__ __nv_bfloat16 g_hb[N_NODES * C];  // bf16 h1 (gather source, layer 2)
__device__ float g_agg[N_NODES * C];         // tf32-rounded gather output
__device__ float g_Wt[4][C * C];       // tf32-pre-rounded W1a, W1b, W2a, W2b
__device__ float g_gsum[NUM_GRAPHS * C];
__device__ float g_gcnt[NUM_GRAPHS];
__device__ int   g_src[N_EDGES];
__device__ int   g_dst[N_EDGES];
__device__ int   g_rank[N_EDGES];
__device__ int   g_csrc[N_NODES * CAP];
__device__ int   g_deg[N_NODES];
__device__ int   g_batch[N_NODES];
__device__ int   g_is64;

// ---------------- helpers ----------------
__device__ __forceinline__ float tf32r(float x) {
    uint32_t u; asm("cvt.rna.tf32.f32 %0, %1;" : "=r"(u) : "f"(x));
    return __uint_as_float(u);
}
__device__ __forceinline__ void mma8(float* c, uint32_t a0, uint32_t a1, uint32_t a2,
                                     uint32_t a3, uint32_t b0, uint32_t b1) {
    asm volatile("mma.sync.aligned.m16n8k8.row.col.f32.tf32.tf32.f32 "
                 "{%0,%1,%2,%3}, {%4,%5,%6,%7}, {%8,%9}, {%0,%1,%2,%3};"
                 : "+f"(c[0]), "+f"(c[1]), "+f"(c[2]), "+f"(c[3])
                 : "r"(a0), "r"(a1), "r"(a2), "r"(a3), "r"(b0), "r"(b1));
}
// bf16 -> f32 is a 16-bit shift; accumulate 8 channels as 4 packed f32x2 adds.
__device__ __forceinline__ void bf8_acc(const __nv_bfloat16* p, unsigned long long* acc) {
    uint4 u = *(const uint4*)p;
    unsigned long long v0, v1, v2, v3;
    asm("mov.b64 %0, {%1, %2};" : "=l"(v0)
        : "r"(u.x << 16), "r"(u.x & 0xffff0000u));
    asm("mov.b64 %0, {%1, %2};" : "=l"(v1)
        : "r"(u.y << 16), "r"(u.y & 0xffff0000u));
    asm("mov.b64 %0, {%1, %2};" : "=l"(v2)
        : "r"(u.z << 16), "r"(u.z & 0xffff0000u));
    asm("mov.b64 %0, {%1, %2};" : "=l"(v3)
        : "r"(u.w << 16), "r"(u.w & 0xffff0000u));
    asm("add.rn.f32x2 %0, %0, %1;" : "+l"(acc[0]) : "l"(v0));
    asm("add.rn.f32x2 %0, %0, %1;" : "+l"(acc[1]) : "l"(v1));
    asm("add.rn.f32x2 %0, %0, %1;" : "+l"(acc[2]) : "l"(v2));
    asm("add.rn.f32x2 %0, %0, %1;" : "+l"(acc[3]) : "l"(v3));
}

// ---------------- mega setup ----------------
__global__ void mega_setup(const float* __restrict__ x,
                           const float* __restrict__ W1a, const float* __restrict__ W1b,
                           const float* __restrict__ W2a, const float* __restrict__ W2b,
                           const int* __restrict__ eidx_raw) {
    int i = blockIdx.x * blockDim.x + threadIdx.x;
    if (i < N_NODES * C / 8) {
        float4 a = ((const float4*)x)[i * 2];
        float4 b = ((const float4*)x)[i * 2 + 1];
        uint4 o;
        __nv_bfloat162 p0 = __float22bfloat162_rn(make_float2(a.x, a.y));
        __nv_bfloat162 p1 = __float22bfloat162_rn(make_float2(a.z, a.w));
        __nv_bfloat162 p2 = __float22bfloat162_rn(make_float2(b.x, b.y));
        __nv_bfloat162 p3 = __float22bfloat162_rn(make_float2(b.z, b.w));
        o.x = *reinterpret_cast<uint32_t*>(&p0);
        o.y = *reinterpret_cast<uint32_t*>(&p1);
        o.z = *reinterpret_cast<uint32_t*>(&p2);
        o.w = *reinterpret_cast<uint32_t*>(&p3);
        ((uint4*)g_xb)[i] = o;
    }
    if (i < 16384) {
        int which = i >> 12;
        int idx = i & 4095;
        const float* src = (which == 0) ? W1a : (which == 1) ? W1b
                         : (which == 2) ? W2a : W2b;
        float4 v = ((const float4*)src)[idx];
        ((float4*)g_Wt[which])[idx] =
            make_float4(tf32r(v.x), tf32r(v.y), tf32r(v.z), tf32r(v.w));
    }
    if (i < N_NODES) g_deg[i] = 0;
    if (i < NUM_GRAPHS * C) g_gsum[i] = 0.f;
    if (i < NUM_GRAPHS) g_gcnt[i] = 0.f;
    if (i == 0) {
        int any = 0;
#pragma unroll
        for (int k = 1; k < 128; k += 2) any |= eidx_raw[k];
        g_is64 = (any == 0) ? 1 : 0;
    }
}

// ---------------- convert indices + degree histogram ----------------
__global__ void convert_indices(const void* __restrict__ eidx,
                                const void* __restrict__ batch) {
    int i0 = (blockIdx.x * blockDim.x + threadIdx.x) * 4;
    if (g_is64) {
        const long long* e = (const long long*)eidx;
        if (i0 < N_EDGES) {
            longlong2 s01 = *(const longlong2*)&e[i0];
            longlong2 s23 = *(const longlong2*)&e[i0 + 2];
            longlong2 d01 = *(const longlong2*)&e[N_EDGES + i0];
            longlong2 d23 = *(const longlong2*)&e[N_EDGES + i0 + 2];
            int4 s = make_int4((int)s01.x, (int)s01.y, (int)s23.x, (int)s23.y);
            int4 d = make_int4((int)d01.x, (int)d01.y, (int)d23.x, (int)d23.y);
            *(int4*)&g_src[i0] = s;
            *(int4*)&g_dst[i0] = d;
            int4 r;
            r.x = atomicAdd(&g_deg[d.x], 1);
            r.y = atomicAdd(&g_deg[d.y], 1);
            r.z = atomicAdd(&g_deg[d.z], 1);
            r.w = atomicAdd(&g_deg[d.w], 1);
            *(int4*)&g_rank[i0] = r;
        }
        if (i0 < N_NODES) {
            const long long* b = (const long long*)batch;
            longlong2 b01 = *(const longlong2*)&b[i0];
            longlong2 b23 = *(const longlong2*)&b[i0 + 2];
            int4 g = make_int4((int)b01.x, (int)b01.y, (int)b23.x, (int)b23.y);
            *(int4*)&g_batch[i0] = g;
            atomicAdd(&g_gcnt[g.x], 1.f); atomicAdd(&g_gcnt[g.y], 1.f);
            atomicAdd(&g_gcnt[g.z], 1.f); atomicAdd(&g_gcnt[g.w], 1.f);
        }
    } else {
        const int* e = (const int*)eidx;
        if (i0 < N_EDGES) {
            int4 s = *(const int4*)&e[i0];
            int4 d = *(const int4*)&e[N_EDGES + i0];
            *(int4*)&g_src[i0] = s;
            *(int4*)&g_dst[i0] = d;
            int4 r;
            r.x = atomicAdd(&g_deg[d.x], 1);
            r.y = atomicAdd(&g_deg[d.y], 1);
            r.z = atomicAdd(&g_deg[d.z], 1);
            r.w = atomicAdd(&g_deg[d.w], 1);
            *(int4*)&g_rank[i0] = r;
        }
        if (i0 < N_NODES) {
            int4 g = *(const int4*)&((const int*)batch)[i0];
            *(int4*)&g_batch[i0] = g;
            atomicAdd(&g_gcnt[g.x], 1.f); atomicAdd(&g_gcnt[g.y], 1.f);
            atomicAdd(&g_gcnt[g.z], 1.f); atomicAdd(&g_gcnt[g.w], 1.f);
        }
    }
}

// ---------------- bucket fill (atomic-free) ----------------
__global__ void fill_csr() {
    int i0 = (blockIdx.x * blockDim.x + threadIdx.x) * 4;
    if (i0 + 3 < N_EDGES) {
        int4 d = *(const int4*)&g_dst[i0];
        int4 s = *(const int4*)&g_src[i0];
        int4 r = *(const int4*)&g_rank[i0];
        if (r.x < CAP) g_csrc[d.x * CAP + r.x] = s.x;
        if (r.y < CAP) g_csrc[d.y * CAP + r.y] = s.y;
        if (r.z < CAP) g_csrc[d.z * CAP + r.z] = s.z;
        if (r.w < CAP) g_csrc[d.w * CAP + r.w] = s.w;
    } else {
        for (int i = i0; i < N_EDGES; ++i) {
            int r = g_rank[i];
            if (r < CAP) g_csrc[g_dst[i] * CAP + r] = g_src[i];
        }
    }
}

// ---------------- standalone gather: high-occupancy, no smem ----------------
// 2 nodes per warp (grid 1250 -> ~68 warps/SM); half-warps pair edges;
// LDG.128 (8 bf16 channels/lane); packed f32x2 accumulation.
__global__ void __launch_bounds__(256) gather_kernel(
    const __nv_bfloat16* __restrict__ feat, float* __restrict__ agg)
{
    const int t = threadIdx.x;
    const int lane = t & 31;
    const int w = t >> 5;
    const int half = lane >> 4;           // 0 or 1
    const int chb = (lane & 15) * 8;      // channel base
#pragma unroll
    for (int i = 0; i < 2; ++i) {
        int node = blockIdx.x * 16 + w * 2 + i;   // grid 1250 -> exact
        unsigned long long acc[4];
        float z = 0.f;
        asm("mov.b64 %0, {%1, %1};" : "=l"(acc[0]) : "f"(z));
        acc[1] = acc[0]; acc[2] = acc[0]; acc[3] = acc[0];
        if (half == 0)                    // self term (GIN eps=0)
            bf8_acc(&feat[(size_t)node * C + chb], acc);
        const int* adj = &g_csrc[node * CAP];
        int deg = g_deg[node];
        if (deg > CAP) deg = CAP;
        int e = 0;
        for (; e + 8 <= deg; e += 8) {
            int s0 = adj[e + half];
            int s1 = adj[e + 2 + half];
            int s2 = adj[e + 4 + half];
            int s3 = adj[e + 6 + half];
            bf8_acc(&feat[(size_t)s0 * C + chb], acc);
            bf8_acc(&feat[(size_t)s1 * C + chb], acc);
            bf8_acc(&feat[(size_t)s2 * C + chb], acc);
            bf8_acc(&feat[(size_t)s3 * C + chb], acc);
        }
        for (; e + 2 <= deg; e += 2) {
            int s = adj[e + half];
            bf8_acc(&feat[(size_t)s * C + chb], acc);
        }
        if (e < deg && half == 0)
            bf8_acc(&feat[(size_t)adj[e] * C + chb], acc);
        // unpack, combine halves, tf32-round, store
        float av[8];
#pragma unroll
        for (int j = 0; j < 4; ++j) {
            uint32_t lo, hi;
            asm("mov.b64 {%0, %1}, %2;" : "=r"(lo), "=r"(hi) : "l"(acc[j]));
            av[j * 2]     = __uint_as_float(lo);
            av[j * 2 + 1] = __uint_as_float(hi);
        }
#pragma unroll
        for (int j = 0; j < 8; ++j)
            av[j] += __shfl_xor_sync(0xFFFFFFFFu, av[j], 16);
        float4 o = (half == 0)
            ? make_float4(tf32r(av[0]), tf32r(av[1]), tf32r(av[2]), tf32r(av[3]))
            : make_float4(tf32r(av[4]), tf32r(av[5]), tf32r(av[6]), tf32r(av[7]));
        *(float4*)&agg[(size_t)node * C + chb + half * 4] = o;
    }
}

// ---------------- MLP kernel: GEMM1 + ReLU + GEMM2 (+pool) ----------------
#define TILE_ROWS 32
#define ASTR 132
#define WSTR 136
#define CONV_SMEM ((128 * WSTR + TILE_ROWS * ASTR) * 4)

__device__ __forceinline__ void gemm_tile(const float* __restrict__ As,
                                          const float* __restrict__ Ws,
                                          float acc[4][4],
                                          int m_base, int n_base, int qid, int tid4)
{
#pragma unroll
    for (int nt = 0; nt < 4; ++nt)
#pragma unroll
        for (int j = 0; j < 4; ++j) acc[nt][j] = 0.f;

#pragma unroll
    for (int k0 = 0; k0 < 128; k0 += 8) {
        const float* ar0 = &As[(m_base + qid) * ASTR + k0 + tid4];
        const float* ar1 = &As[(m_base + qid + 8) * ASTR + k0 + tid4];
        uint32_t a0 = __float_as_uint(ar0[0]);
        uint32_t a1 = __float_as_uint(ar1[0]);
        uint32_t a2 = __float_as_uint(ar0[4]);
        uint32_t a3 = __float_as_uint(ar1[4]);
        const float* wr0 = &Ws[(k0 + tid4) * WSTR + n_base + qid];
        const float* wr1 = wr0 + 4 * WSTR;
#pragma unroll
        for (int nt = 0; nt < 4; ++nt) {
            uint32_t b0 = __float_as_uint(wr0[nt * 8]);
            uint32_t b1 = __float_as_uint(wr1[nt * 8]);
            mma8(acc[nt], a0, a1, a2, a3, b0, b1);
        }
    }
}

__global__ void __launch_bounds__(256, 2) mlp_kernel(
    const float* __restrict__ agg,
    const float* __restrict__ Wa, const float* __restrict__ ba,
    const float* __restrict__ Wb, const float* __restrict__ bb,
    __nv_bfloat16* __restrict__ outb, int do_pool)
{
    extern __shared__ float sm[];
    float* Ws = sm;                       // [128][WSTR]
    float* As = sm + 128 * WSTR;          // [32][ASTR]

    const int t = threadIdx.x;
    const int m0 = blockIdx.x * TILE_ROWS;
    const int lane = t & 31;
    const int w = t >> 5;

    // load Wa (pure copy, pre-rounded)
#pragma unroll
    for (int i = 0; i < 16; ++i) {
        int idx = t + i * 256;
        float4 v = ((const float4*)Wa)[idx];
        *(float4*)&Ws[(idx >> 5) * WSTR + (idx & 31) * 4] = v;
    }
    // load A tile (coalesced; already tf32-rounded)
#pragma unroll
    for (int i = 0; i < 4; ++i) {
        int idx = t + i * 256;            // 1024 float4
        int r = idx >> 5;
        int c4 = idx & 31;
        float4 v = ((const float4*)agg)[(size_t)(m0 + r) * 32 + c4];
        *(float4*)&As[r * ASTR + c4 * 4] = v;
    }
    __syncthreads();

    const int warp_m = w & 1;
    const int warp_n = w >> 1;
    const int m_base = warp_m * 16;
    const int n_base = warp_n * 32;
    const int qid = lane >> 2;
    const int tid4 = lane & 3;

    float acc[4][4];

    // GEMM1
    gemm_tile(As, Ws, acc, m_base, n_base, qid, tid4);
    __syncthreads();

    // t = tf32(relu(acc + ba)) -> As ; reload Ws with Wb
#pragma unroll
    for (int nt = 0; nt < 4; ++nt) {
        int col = n_base + nt * 8 + 2 * tid4;
        float2 bv = *(const float2*)&ba[col];
        int r0 = m_base + qid, r1 = r0 + 8;
        *(float2*)&As[r0 * ASTR + col] =
            make_float2(tf32r(fmaxf(acc[nt][0] + bv.x, 0.f)),
                        tf32r(fmaxf(acc[nt][1] + bv.y, 0.f)));
        *(float2*)&As[r1 * ASTR + col] =
            make_float2(tf32r(fmaxf(acc[nt][2] + bv.x, 0.f)),
                        tf32r(fmaxf(acc[nt][3] + bv.y, 0.f)));
    }
#pragma unroll
    for (int i = 0; i < 16; ++i) {
        int idx = t + i * 256;
        float4 v = ((const float4*)Wb)[idx];
        *(float4*)&Ws[(idx >> 5) * WSTR + (idx & 31) * 4] = v;
    }
    __syncthreads();

    // GEMM2
    gemm_tile(As, Ws, acc, m_base, n_base, qid, tid4);

    // epilogue
    const int rowA = m0 + m_base + qid;
    const int rowB = rowA + 8;
    if (do_pool) {
        int gA = g_batch[rowA];
        int gB = g_batch[rowB];
#pragma unroll
        for (int nt = 0; nt < 4; ++nt) {
            int col = n_base + nt * 8 + 2 * tid4;
            float2 bv = *(const float2*)&bb[col];
            float v0 = fmaxf(acc[nt][0] + bv.x, 0.f);
            float v1 = fmaxf(acc[nt][1] + bv.y, 0.f);
            float v2 = fmaxf(acc[nt][2] + bv.x, 0.f);
            float v3 = fmaxf(acc[nt][3] + bv.y, 0.f);
            if (gA == gB) {
                atomicAdd(&g_gsum[gA * C + col],     v0 + v2);
                atomicAdd(&g_gsum[gA * C + col + 1], v1 + v3);
            } else {
                atomicAdd(&g_gsum[gA * C + col],     v0);
                atomicAdd(&g_gsum[gA * C + col + 1], v1);
                atomicAdd(&g_gsum[gB * C + col],     v2);
                atomicAdd(&g_gsum[gB * C + col + 1], v3);
            }
        }
    } else {
#pragma unroll
        for (int nt = 0; nt < 4; ++nt) {
            int col = n_base + nt * 8 + 2 * tid4;
            float2 bv = *(const float2*)&bb[col];
            __nv_bfloat162 pA = __float22bfloat162_rn(
                make_float2(fmaxf(acc[nt][0] + bv.x, 0.f), fmaxf(acc[nt][1] + bv.y, 0.f)));
            __nv_bfloat162 pB = __float22bfloat162_rn(
                make_float2(fmaxf(acc[nt][2] + bv.x, 0.f), fmaxf(acc[nt][3] + bv.y, 0.f)));
            *(__nv_bfloat162*)&outb[(size_t)rowA * C + col] = pA;
            *(__nv_bfloat162*)&outb[(size_t)rowB * C + col] = pB;
        }
    }
}

// ---------------- finalize ----------------
__global__ void finalize_kernel(const float* __restrict__ fc_w,
                                const float* __restrict__ fc_b,
                                float* __restrict__ out) {
    int g = blockIdx.x;
    int t = threadIdx.x;  // 128
    float v = g_gsum[g * C + t] * fc_w[t];
#pragma unroll
    for (int o = 16; o > 0; o >>= 1) v += __shfl_down_sync(0xFFFFFFFFu, v, o);
    __shared__ float ws[4];
    if ((t & 31) == 0) ws[t >> 5] = v;
    __syncthreads();
    if (t == 0) {
        float s = ws[0] + ws[1] + ws[2] + ws[3];
        out[g] = s / fmaxf(g_gcnt[g], 1.0f) + fc_b[0];
    }
}

// ---------------- launch ----------------
extern "C" void kernel_launch(void* const* d_in, const int* in_sizes, int n_in,
                              void* d_out, int out_size) {
    const float* x    = (const float*)d_in[0];
    const void*  eidx = d_in[1];
    const void*  batv = d_in[2];
    const float* W1a  = (const float*)d_in[3];
    const float* b1a  = (const float*)d_in[4];
    const float* W1b  = (const float*)d_in[5];
    const float* b1b  = (const float*)d_in[6];
    const float* W2a  = (const float*)d_in[7];
    const float* b2a  = (const float*)d_in[8];
    const float* W2b  = (const float*)d_in[9];
    const float* b2b  = (const float*)d_in[10];
    const float* fcw  = (const float*)d_in[11];
    const float* fcb  = (const float*)d_in[12];
    float* out = (float*)d_out;
    (void)in_sizes; (void)n_in; (void)out_size;

    cudaFuncSetAttribute(mlp_kernel,
                         cudaFuncAttributeMaxDynamicSharedMemorySize, CONV_SMEM);

    float *p_Wt, *p_agg;
    __nv_bfloat16 *p_xb, *p_hb;
    cudaGetSymbolAddress((void**)&p_Wt,  g_Wt);
    cudaGetSymbolAddress((void**)&p_agg, g_agg);
    cudaGetSymbolAddress((void**)&p_xb,  g_xb);
    cudaGetSymbolAddress((void**)&p_hb,  g_hb);

    const int mlp_blocks = N_NODES / TILE_ROWS;      // 625, exact
    const int gather_blocks = N_NODES / 16;          // 1250, exact

    // #1: setup + W preround + x->bf16
    mega_setup<<<(N_NODES * C / 8 + 255) / 256, 256>>>(
        x, W1a, W1b, W2a, W2b, (const int*)eidx);
    // #2: index convert + degree histogram
    convert_indices<<<(N_EDGES / 4 + 255) / 256, 256>>>(eidx, batv);
    // #3: bucket fill
    fill_csr<<<(N_EDGES / 4 + 255) / 256, 256>>>();
    // #4 (ncu-profiled): gather layer 1
    gather_kernel<<<gather_blocks, 256>>>(p_xb, p_agg);
    // #5: MLP layer 1 -> h1 (bf16)
    mlp_kernel<<<mlp_blocks, 256, CONV_SMEM>>>(
        p_agg, p_Wt + 0 * C * C, b1a, p_Wt + 1 * C * C, b1b, p_hb, 0);
    // #6: gather layer 2
    gather_kernel<<<gather_blocks, 256>>>(p_hb, p_agg);
    // #7: MLP layer 2 (+ fused pool)
    mlp_kernel<<<mlp_blocks, 256, CONV_SMEM>>>(
        p_agg, p_Wt + 2 * C * C, b2a, p_Wt + 3 * C * C, b2b, nullptr, 1);
    // #8: finalize
    finalize_kernel<<<NUM_GRAPHS, C>>>(fcw, fcb, out);
}